// round 11
// baseline (speedup 1.0000x reference)
#include <cuda_runtime.h>
#include <cuda_bf16.h>
#include <cstdint>
#include <math.h>

// Problem constants (fixed by setup_inputs)
#define NB   8
#define NQL  8192
#define NVL  16384      // 128*128
#define EDIM 256
#define NH   8
#define DH   32
#define NP   4
#define WGRID 128
#define HGRID 128

// ---------------------------------------------------------------------------
// Device scratch (allocation-free per harness rules)
// ---------------------------------------------------------------------------
__device__ float g_v[(size_t)NB * NVL * EDIM];       // projected value  [B, NV, 256]
__device__ float g_mid[(size_t)NB * NQL * EDIM];     // sampled output   [B, NQ, 256]
__device__ float g_logit[(size_t)NB * NQL * 128];    // offsets(64)+attn(32)+pad(32)
// Packed weights, bf16 hi/lo planes, row-major [n][k]
//   rows   0..255 : W_val ; rows 256..383 : [W_off|W_attn|0] ; rows 384..639 : W_out
__device__ __nv_bfloat16 g_bhi[640 * 256];
__device__ __nv_bfloat16 g_blo[640 * 256];
__device__ float g_biasp[640];

// ---------------------------------------------------------------------------
// Helpers (compute_103-legal PTX only: mma.sync + ldmatrix)
// ---------------------------------------------------------------------------
__device__ __forceinline__ uint32_t smem_u32(const void* p) {
    uint32_t a;
    asm("{ .reg .u64 t; cvta.to.shared.u64 t, %1; cvt.u32.u64 %0, t; }"
        : "=r"(a) : "l"(p));
    return a;
}

__device__ __forceinline__ void ldm_x4(uint32_t* r, uint32_t addr) {
    asm volatile("ldmatrix.sync.aligned.m8n8.x4.shared.b16 {%0,%1,%2,%3}, [%4];"
        : "=r"(r[0]), "=r"(r[1]), "=r"(r[2]), "=r"(r[3]) : "r"(addr));
}

__device__ __forceinline__ void mma16816(float* c, const uint32_t* a,
                                         const uint32_t* b) {
    asm volatile(
        "mma.sync.aligned.m16n8k16.row.col.f32.bf16.bf16.f32 "
        "{%0,%1,%2,%3}, {%4,%5,%6,%7}, {%8,%9}, {%0,%1,%2,%3};"
        : "+f"(c[0]), "+f"(c[1]), "+f"(c[2]), "+f"(c[3])
        : "r"(a[0]), "r"(a[1]), "r"(a[2]), "r"(a[3]), "r"(b[0]), "r"(b[1]));
}

// fp32 pair -> bf16x2 hi plane + bf16x2 lo (residual) plane (fast path)
__device__ __forceinline__ void cvt_hilo(float x, float y,
                                         uint32_t& h, uint32_t& l) {
    asm("cvt.rn.bf16x2.f32 %0, %1, %2;" : "=r"(h) : "f"(y), "f"(x)); // hi=y lo=x
    float hx = __uint_as_float(__byte_perm(0u, h, 0x5400));
    float hy = __uint_as_float(__byte_perm(0u, h, 0x7600));
    float lx = x - hx, ly = y - hy;
    asm("cvt.rn.bf16x2.f32 %0, %1, %2;" : "=r"(l) : "f"(ly), "f"(lx));
}

// ---------------------------------------------------------------------------
// Prep kernel: pack weights to bf16 hi/lo planes [n][k] + packed biases
// ---------------------------------------------------------------------------
__global__ __launch_bounds__(256) void pack_w_k(
    const float* __restrict__ Wval, const float* __restrict__ Woff,
    const float* __restrict__ Wattn, const float* __restrict__ Wout,
    const float* __restrict__ bval, const float* __restrict__ boff,
    const float* __restrict__ battn, const float* __restrict__ bout)
{
    int n = blockIdx.x;     // 0..639
    int k = threadIdx.x;    // 0..255
    float w, bv;
    if (n < 256) {
        w = Wval[(size_t)k * 256 + n];  bv = bval[n];
    } else if (n < 384) {
        int n2 = n - 256;
        w  = (n2 < 64) ? Woff[(size_t)k * 64 + n2]
                       : (n2 < 96 ? Wattn[(size_t)k * 32 + (n2 - 64)] : 0.f);
        bv = (n2 < 64) ? boff[n2] : (n2 < 96 ? battn[n2 - 64] : 0.f);
    } else {
        int n2 = n - 384;
        w = Wout[(size_t)k * 256 + n2];  bv = bout[n2];
    }
    __nv_bfloat16 h = __float2bfloat16(w);
    __nv_bfloat16 l = __float2bfloat16(w - __bfloat162float(h));
    g_bhi[(size_t)n * 256 + k] = h;
    g_blo[(size_t)n * 256 + k] = l;
    if (k == 0) g_biasp[n] = bv;
}

// ---------------------------------------------------------------------------
// Shared GEMM pieces
// ---------------------------------------------------------------------------
#define BROW 264                     // padded bf16 elems per B smem row
#define BPLANE (128 * BROW)          // elems per plane
#define GSMEM (2 * BPLANE * 2)       // bytes (hi + lo)

// Stage a 128-row packed weight slice (hi/lo) into padded SMEM layout.
__device__ __forceinline__ void stage_b(
    __nv_bfloat16* bsm, int wrow, int tid)
{
    const uint32_t* srcH = (const uint32_t*)(g_bhi + (size_t)wrow * 256);
    const uint32_t* srcL = (const uint32_t*)(g_blo + (size_t)wrow * 256);
    uint32_t* dstH = (uint32_t*)bsm;
    uint32_t* dstL = (uint32_t*)(bsm + BPLANE);
    for (int i = tid; i < 128 * 128; i += 256) {
        int n = i >> 7, kk = i & 127;
        dstH[n * (BROW / 2) + kk] = srcH[i];
        dstL[n * (BROW / 2) + kk] = srcL[i];
    }
}

// Mainloop + epilogue for one 128x128 output tile.
__device__ __forceinline__ void gemm_tile(
    const float* __restrict__ A, float* __restrict__ C,
    const float* __restrict__ res,
    size_t m0, int n0, int ldc,
    const float2* bb, uint32_t sbase, uint32_t rowb,
    int wm, int wn, int g, int qc)
{
    float c[2][8][4];
    #pragma unroll
    for (int i = 0; i < 2; i++)
        #pragma unroll
        for (int j = 0; j < 8; j++)
            c[i][j][0] = c[i][j][1] = c[i][j][2] = c[i][j][3] = 0.f;

    const float* a0 = A + (m0 + wm * 32 + g) * 256 + qc;
    const float* a1 = a0 + 16 * 256;

    float2 vbuf[2][2][4];
    {
        vbuf[0][0][0] = *(const float2*)(a0);
        vbuf[0][0][1] = *(const float2*)(a0 + 2048);
        vbuf[0][0][2] = *(const float2*)(a0 + 8);
        vbuf[0][0][3] = *(const float2*)(a0 + 2056);
        vbuf[0][1][0] = *(const float2*)(a1);
        vbuf[0][1][1] = *(const float2*)(a1 + 2048);
        vbuf[0][1][2] = *(const float2*)(a1 + 8);
        vbuf[0][1][3] = *(const float2*)(a1 + 2056);
    }

    #pragma unroll 4
    for (int ks = 0; ks < 16; ks++) {
        const int k0 = ks * 16;
        float2 (&v)[2][4] = vbuf[ks & 1];

        if (ks < 15) {
            float2 (&vn)[2][4] = vbuf[(ks + 1) & 1];
            const float* p0 = a0 + k0 + 16;
            const float* p1 = a1 + k0 + 16;
            vn[0][0] = *(const float2*)(p0);
            vn[0][1] = *(const float2*)(p0 + 2048);
            vn[0][2] = *(const float2*)(p0 + 8);
            vn[0][3] = *(const float2*)(p0 + 2056);
            vn[1][0] = *(const float2*)(p1);
            vn[1][1] = *(const float2*)(p1 + 2048);
            vn[1][2] = *(const float2*)(p1 + 8);
            vn[1][3] = *(const float2*)(p1 + 2056);
        }

        uint32_t ah[2][4], al[2][4];
        #pragma unroll
        for (int i = 0; i < 2; i++) {
            cvt_hilo(v[i][0].x, v[i][0].y, ah[i][0], al[i][0]);
            cvt_hilo(v[i][1].x, v[i][1].y, ah[i][1], al[i][1]);
            cvt_hilo(v[i][2].x, v[i][2].y, ah[i][2], al[i][2]);
            cvt_hilo(v[i][3].x, v[i][3].y, ah[i][3], al[i][3]);
        }

        uint32_t bh[8][2], bl[8][2];
        #pragma unroll
        for (int jj = 0; jj < 4; jj++) {
            uint32_t off =
                (uint32_t)(((wn * 64 + jj * 16) * BROW + k0) * 2) + rowb;
            uint32_t r4[4];
            ldm_x4(r4, sbase + off);
            bh[2 * jj][0] = r4[0]; bh[2 * jj][1] = r4[1];
            bh[2 * jj + 1][0] = r4[2]; bh[2 * jj + 1][1] = r4[3];
            ldm_x4(r4, sbase + 2 * BPLANE + off);
            bl[2 * jj][0] = r4[0]; bl[2 * jj][1] = r4[1];
            bl[2 * jj + 1][0] = r4[2]; bl[2 * jj + 1][1] = r4[3];
        }

        #pragma unroll
        for (int i = 0; i < 2; i++)
            #pragma unroll
            for (int j = 0; j < 8; j++) {
                mma16816(c[i][j], ah[i], bh[j]);
                mma16816(c[i][j], ah[i], bl[j]);
                mma16816(c[i][j], al[i], bh[j]);
            }
    }

    #pragma unroll
    for (int i = 0; i < 2; i++) {
        size_t row = m0 + wm * 32 + i * 16 + g;
        #pragma unroll
        for (int j = 0; j < 8; j++) {
            int col = n0 + wn * 64 + j * 8 + qc;
            float2 o0, o1;
            o0.x = c[i][j][0] + bb[j].x;
            o0.y = c[i][j][1] + bb[j].y;
            o1.x = c[i][j][2] + bb[j].x;
            o1.y = c[i][j][3] + bb[j].y;
            if (res) {
                float2 r0 = *(const float2*)(res + row * (size_t)ldc + col);
                float2 r1 = *(const float2*)(res + (row + 8) * (size_t)ldc + col);
                o0.x += r0.x; o0.y += r0.y;
                o1.x += r1.x; o1.y += r1.y;
            }
            *(float2*)(C + row * (size_t)ldc + col) = o0;
            *(float2*)(C + (row + 8) * (size_t)ldc + col) = o1;
        }
    }
}

// ---------------------------------------------------------------------------
// Fused GEMM 1+2: one persistent launch over a global job list.
//   jobs    0..1023 : slice 0 = value @ Wval cols   0..127 -> g_v
//   jobs 1024..2047 : slice 1 = value @ Wval cols 128..255 -> g_v
//   jobs 2048..2559 : slice 2 = query @ [Woff|Wattn|0]     -> g_logit
// Contiguous chunks per CTA -> at most 2 B re-stagings per CTA.
// ---------------------------------------------------------------------------
__global__ __launch_bounds__(256) void hmma_fused12_k(
    const float* __restrict__ value, const float* __restrict__ query)
{
    extern __shared__ __nv_bfloat16 bsm[];
    const int tid = threadIdx.x, lane = tid & 31, wid = tid >> 5;
    const int wm = wid & 3, wn = wid >> 2;
    const int g  = lane >> 2;
    const int qc = (lane & 3) * 2;

    const uint32_t sbase = smem_u32(bsm);
    const int lm = lane >> 3, lr = lane & 7;
    const uint32_t rowb =
        (uint32_t)((((lm >> 1) * 8 + lr) * BROW + (lm & 1) * 8) * 2);

    // balanced contiguous job ranges: 2560 jobs over 148 CTAs (44 get 18)
    int bid = blockIdx.x;
    int start = bid * 17 + min(bid, 44);
    int end = start + 17 + (bid < 44 ? 1 : 0);

    int curSlice = -1;
    const float* A = value;
    float* C = g_v;
    int n0 = 0, ldc = 256, sbaseJob = 0;
    float2 bb[8];

    for (int job = start; job < end; job++) {
        int slice = (job >= 2048) ? 2 : (job >> 10);
        if (slice != curSlice) {
            __syncthreads();                     // all warps done with old B
            int wrow = (slice == 2) ? 256 : (slice << 7);
            stage_b(bsm, wrow, tid);
            __syncthreads();
            curSlice = slice;
            n0  = (slice == 1) ? 128 : 0;
            ldc = (slice == 2) ? 128 : 256;
            A   = (slice == 2) ? query : value;
            C   = (slice == 2) ? g_logit : g_v;
            sbaseJob = (slice == 2) ? 2048 : (slice << 10);
            #pragma unroll
            for (int j = 0; j < 8; j++)
                bb[j] = *(const float2*)(g_biasp + wrow + wn * 64 + j * 8 + qc);
        }
        size_t m0 = (size_t)(job - sbaseJob) << 7;
        gemm_tile(A, C, nullptr, m0, n0, ldc, bb, sbase, rowb, wm, wn, g, qc);
    }
}

// ---------------------------------------------------------------------------
// Standalone GEMM (output projection): C = g_mid @ Wout + bias + residual
// ---------------------------------------------------------------------------
__global__ __launch_bounds__(256) void hmma_gemm_k(
    const float* __restrict__ A,
    const float* __restrict__ biasp,
    const float* __restrict__ res,
    float* __restrict__ C, int M, int ldc)
{
    extern __shared__ __nv_bfloat16 bsm[];
    const int tid = threadIdx.x, lane = tid & 31, wid = tid >> 5;
    const int wm = wid & 3, wn = wid >> 2;
    const int n0 = blockIdx.x * 128;
    const int g  = lane >> 2;
    const int qc = (lane & 3) * 2;

    stage_b(bsm, 384 + n0, tid);     // W_out rows start at 384
    __syncthreads();

    float2 bb[8];
    #pragma unroll
    for (int j = 0; j < 8; j++)
        bb[j] = *(const float2*)(biasp + 384 + n0 + wn * 64 + j * 8 + qc);

    const uint32_t sbase = smem_u32(bsm);
    const int lm = lane >> 3, lr = lane & 7;
    const uint32_t rowb =
        (uint32_t)((((lm >> 1) * 8 + lr) * BROW + (lm & 1) * 8) * 2);

    const int ntiles = M >> 7;
    for (int tile = blockIdx.y; tile < ntiles; tile += gridDim.y) {
        gemm_tile(A, C, res, (size_t)tile << 7, n0, ldc, bb,
                  sbase, rowb, wm, wn, g, qc);
    }
}

// ---------------------------------------------------------------------------
// Sampler, two-phase:
//  setup : precompute, per (q,h,p): 4 final BYTE offsets into the value slice
//          + softmax-folded validity-zeroed corner weights.
//  gather: warp = head, lane = channel; LDS.128 x2 + 4x(add+LDG+FFMA).
// ---------------------------------------------------------------------------
__global__ __launch_bounds__(256) void sample_k(const float* __restrict__ ref2d)
{
    __shared__ float  lg[16][128];
    __shared__ float  refs[32];
    __shared__ int4   smO[512];       // [q][h][p] byte offsets of 4 corners
    __shared__ float4 smW[512];       // [q][h][p] folded corner weights

    int tid = threadIdx.x;
    int b  = blockIdx.x >> 9;            // 512 blocks per batch
    int q0 = (blockIdx.x & 511) << 4;

    const float4* lsrc = (const float4*)(g_logit + ((size_t)b * NQL + q0) * 128);
    #pragma unroll
    for (int i = 0; i < 2; i++) {
        int f = tid + i * 256;
        ((float4*)&lg[0][0])[f] = lsrc[f];
    }
    if (tid < 32) refs[tid] = ref2d[((size_t)b * NQL + q0) * 2 + tid];
    __syncthreads();

    // ---- setup: 2 threads per (q,h), 2 points each ----
    {
        int cb = tid >> 1;               // 0..127 = q*8+h
        int q  = cb >> 3, h = cb & 7;
        int pbase = (tid & 1) * 2;

        float l0 = lg[q][64 + h * 4 + 0];
        float l1 = lg[q][64 + h * 4 + 1];
        float l2 = lg[q][64 + h * 4 + 2];
        float l3 = lg[q][64 + h * 4 + 3];
        float m = fmaxf(fmaxf(l0, l1), fmaxf(l2, l3));
        float e0 = __expf(l0 - m), e1 = __expf(l1 - m);
        float e2 = __expf(l2 - m), e3 = __expf(l3 - m);
        float inv = 1.f / (e0 + e1 + e2 + e3);
        float aw[4] = {e0 * inv, e1 * inv, e2 * inv, e3 * inv};

        float refx = refs[2 * q], refy = refs[2 * q + 1];

        #pragma unroll
        for (int pp = 0; pp < 2; pp++) {
            int p = pbase + pp;
            float offx = lg[q][h * 8 + 2 * p + 0];
            float offy = lg[q][h * 8 + 2 * p + 1];
            float x = fmaf(refx, (float)WGRID, offx) - 0.5f;
            float y = fmaf(refy, (float)HGRID, offy) - 0.5f;
            float x0f = floorf(x), y0f = floorf(y);
            int ix0 = (int)x0f, iy0 = (int)y0f;
            int ix1 = ix0 + 1, iy1 = iy0 + 1;
            float wx1 = x - x0f, wx0 = 1.f - wx1;
            float wy1 = y - y0f, wy0 = 1.f - wy1;

            bool vx0 = (unsigned)ix0 < WGRID;
            bool vx1 = (unsigned)ix1 < WGRID;
            bool vy0 = (unsigned)iy0 < HGRID;
            bool vy1 = (unsigned)iy1 < HGRID;

            float ap = aw[p];
            float4 w;
            w.x = (vx0 & vy0) ? ap * wx0 * wy0 : 0.f;
            w.y = (vx1 & vy0) ? ap * wx1 * wy0 : 0.f;
            w.z = (vx0 & vy1) ? ap * wx0 * wy1 : 0.f;
            w.w = (vx1 & vy1) ? ap * wx1 * wy1 : 0.f;

            int x0c = min(max(ix0, 0), WGRID - 1);
            int x1c = min(max(ix1, 0), WGRID - 1);
            int y0c = min(max(iy0, 0), HGRID - 1);
            int y1c = min(max(iy1, 0), HGRID - 1);

            // byte offsets: ((y*128 + x) * 256 floats) * 4B = ((y<<7)+x)<<10
            int r0 = y0c << 7, r1 = y1c << 7;
            int idx = cb * 4 + p;
            smO[idx] = make_int4((r0 + x0c) << 10, (r0 + x1c) << 10,
                                 (r1 + x0c) << 10, (r1 + x1c) << 10);
            smW[idx] = w;
        }
    }
    __syncthreads();

    // ---- gather ----
    int h = tid >> 5, lane = tid & 31;
    const char* vbc = (const char*)(g_v + (size_t)b * NVL * EDIM + h * DH + lane);
    float* mb = g_mid + ((size_t)b * NQL + q0) * EDIM + h * DH + lane;

    #pragma unroll 4
    for (int q = 0; q < 16; q++) {
        int base = (q * 8 + h) * 4;
        float out = 0.f;
        #pragma unroll
        for (int p = 0; p < NP; p++) {
            int4   o = smO[base + p];
            float4 w = smW[base + p];
            out = fmaf(w.x, *(const float*)(vbc + o.x), out);
            out = fmaf(w.y, *(const float*)(vbc + o.y), out);
            out = fmaf(w.z, *(const float*)(vbc + o.z), out);
            out = fmaf(w.w, *(const float*)(vbc + o.w), out);
        }
        mb[(size_t)q * EDIM] = out;
    }
}

// ---------------------------------------------------------------------------
extern "C" void kernel_launch(void* const* d_in, const int* in_sizes, int n_in,
                              void* d_out, int out_size)
{
    const float* query = (const float*)d_in[0];
    const float* value = (const float*)d_in[1];
    const float* ref2d = (const float*)d_in[2];
    // d_in[3] spatial_shapes: fixed 128x128, hardcoded
    const float* Woff  = (const float*)d_in[4];
    const float* boff  = (const float*)d_in[5];
    const float* Wattn = (const float*)d_in[6];
    const float* battn = (const float*)d_in[7];
    const float* Wval  = (const float*)d_in[8];
    const float* bval  = (const float*)d_in[9];
    const float* Wout  = (const float*)d_in[10];
    const float* bout  = (const float*)d_in[11];
    float* out = (float*)d_out;

    float *midptr, *bpf;
    cudaGetSymbolAddress((void**)&midptr, g_mid);
    cudaGetSymbolAddress((void**)&bpf,    g_biasp);

    cudaFuncSetAttribute(hmma_fused12_k,
                         cudaFuncAttributeMaxDynamicSharedMemorySize, GSMEM);
    cudaFuncSetAttribute(hmma_gemm_k,
                         cudaFuncAttributeMaxDynamicSharedMemorySize, GSMEM);

    // 0) pack all weights -> bf16 hi/lo planes (+ padded biases)
    pack_w_k<<<640, 256>>>(Wval, Woff, Wattn, Wout, bval, boff, battn, bout);

    // 1+2) fused: value projection -> g_v  AND  logits -> g_logit
    hmma_fused12_k<<<148, 256, GSMEM>>>(value, query);

    // 3) softmax + bilinear sampling -> g_mid
    sample_k<<<NB * NQL / 16, 256>>>(ref2d);

    // 4) output projection + bias + residual -> out
    hmma_gemm_k<<<dim3(2, 74), 256, GSMEM>>>(
        midptr, bpf, query, out, NB * NQL, 256);
}

// round 12
// speedup vs baseline: 1.0406x; 1.0406x over previous
#include <cuda_runtime.h>
#include <cuda_bf16.h>
#include <cstdint>
#include <math.h>

// Problem constants (fixed by setup_inputs)
#define NB   8
#define NQL  8192
#define NVL  16384      // 128*128
#define EDIM 256
#define NH   8
#define DH   32
#define NP   4
#define WGRID 128
#define HGRID 128

// ---------------------------------------------------------------------------
// Device scratch (allocation-free per harness rules)
// ---------------------------------------------------------------------------
__device__ float g_v[(size_t)NB * NVL * EDIM];       // projected value  [B, NV, 256]
__device__ float g_mid[(size_t)NB * NQL * EDIM];     // sampled output   [B, NQ, 256]
__device__ float g_logit[(size_t)NB * NQL * 128];    // offsets(64)+attn(32)+pad(32)
// Packed weights, bf16 hi/lo planes, row-major [n][k]
//   rows   0..255 : W_val ; rows 256..383 : [W_off|W_attn|0] ; rows 384..639 : W_out
__device__ __nv_bfloat16 g_bhi[640 * 256];
__device__ __nv_bfloat16 g_blo[640 * 256];
__device__ float g_biasp[640];

// ---------------------------------------------------------------------------
// Helpers (compute_103-legal PTX only: mma.sync + ldmatrix)
// ---------------------------------------------------------------------------
__device__ __forceinline__ uint32_t smem_u32(const void* p) {
    uint32_t a;
    asm("{ .reg .u64 t; cvta.to.shared.u64 t, %1; cvt.u32.u64 %0, t; }"
        : "=r"(a) : "l"(p));
    return a;
}

__device__ __forceinline__ void ldm_x4(uint32_t* r, uint32_t addr) {
    asm volatile("ldmatrix.sync.aligned.m8n8.x4.shared.b16 {%0,%1,%2,%3}, [%4];"
        : "=r"(r[0]), "=r"(r[1]), "=r"(r[2]), "=r"(r[3]) : "r"(addr));
}

__device__ __forceinline__ void mma16816(float* c, const uint32_t* a,
                                         const uint32_t* b) {
    asm volatile(
        "mma.sync.aligned.m16n8k16.row.col.f32.bf16.bf16.f32 "
        "{%0,%1,%2,%3}, {%4,%5,%6,%7}, {%8,%9}, {%0,%1,%2,%3};"
        : "+f"(c[0]), "+f"(c[1]), "+f"(c[2]), "+f"(c[3])
        : "r"(a[0]), "r"(a[1]), "r"(a[2]), "r"(a[3]), "r"(b[0]), "r"(b[1]));
}

// fp32 pair -> bf16x2 hi plane + bf16x2 lo (residual) plane (fast path)
__device__ __forceinline__ void cvt_hilo(float x, float y,
                                         uint32_t& h, uint32_t& l) {
    asm("cvt.rn.bf16x2.f32 %0, %1, %2;" : "=r"(h) : "f"(y), "f"(x)); // hi=y lo=x
    float hx = __uint_as_float(__byte_perm(0u, h, 0x5400));
    float hy = __uint_as_float(__byte_perm(0u, h, 0x7600));
    float lx = x - hx, ly = y - hy;
    asm("cvt.rn.bf16x2.f32 %0, %1, %2;" : "=r"(l) : "f"(ly), "f"(lx));
}

// ---------------------------------------------------------------------------
// Prep kernel: pack weights to bf16 hi/lo planes [n][k] + packed biases
// ---------------------------------------------------------------------------
__global__ __launch_bounds__(256) void pack_w_k(
    const float* __restrict__ Wval, const float* __restrict__ Woff,
    const float* __restrict__ Wattn, const float* __restrict__ Wout,
    const float* __restrict__ bval, const float* __restrict__ boff,
    const float* __restrict__ battn, const float* __restrict__ bout)
{
    int n = blockIdx.x;     // 0..639
    int k = threadIdx.x;    // 0..255
    float w, bv;
    if (n < 256) {
        w = Wval[(size_t)k * 256 + n];  bv = bval[n];
    } else if (n < 384) {
        int n2 = n - 256;
        w  = (n2 < 64) ? Woff[(size_t)k * 64 + n2]
                       : (n2 < 96 ? Wattn[(size_t)k * 32 + (n2 - 64)] : 0.f);
        bv = (n2 < 64) ? boff[n2] : (n2 < 96 ? battn[n2 - 64] : 0.f);
    } else {
        int n2 = n - 384;
        w = Wout[(size_t)k * 256 + n2];  bv = bout[n2];
    }
    __nv_bfloat16 h = __float2bfloat16(w);
    __nv_bfloat16 l = __float2bfloat16(w - __bfloat162float(h));
    g_bhi[(size_t)n * 256 + k] = h;
    g_blo[(size_t)n * 256 + k] = l;
    if (k == 0) g_biasp[n] = bv;
}

// ---------------------------------------------------------------------------
// GEMM: 512 threads = 16 warps (4M x 4N), warp tile 32x32, CTA tile 128x128.
// B slice (hi/lo bf16, padded) SMEM-resident; A streamed with double-buffered
// register prefetch; split-bf16: D = Ah*Bh + Ah*Bl + Al*Bh.
// ---------------------------------------------------------------------------
#define BROW 264                     // padded bf16 elems per B smem row
#define BPLANE (128 * BROW)          // elems per plane
#define GSMEM (2 * BPLANE * 2)       // bytes (hi + lo)
#define NTHR 512

__global__ __launch_bounds__(NTHR) void hmma_gemm_k(
    const float* __restrict__ A,
    const float* __restrict__ res,
    float* __restrict__ C,
    int wrow,                        // base row into g_bhi/g_blo/g_biasp
    int M, int ldc)
{
    extern __shared__ __nv_bfloat16 bsm[];   // [hi: 128 x BROW][lo: 128 x BROW]
    const int tid = threadIdx.x, lane = tid & 31, wid = tid >> 5;
    const int wm = wid & 3, wn = wid >> 2;   // warp grid 4M x 4N
    const int n0 = blockIdx.x * 128;
    const int g  = lane >> 2;
    const int qc = (lane & 3) * 2;

    // ---- stage B slice (hi/lo), row-padded for conflict-free ldmatrix ----
    {
        const uint32_t* srcH = (const uint32_t*)(g_bhi + (size_t)(wrow + n0) * 256);
        const uint32_t* srcL = (const uint32_t*)(g_blo + (size_t)(wrow + n0) * 256);
        uint32_t* dstH = (uint32_t*)bsm;
        uint32_t* dstL = (uint32_t*)(bsm + BPLANE);
        for (int i = tid; i < 128 * 128; i += NTHR) {
            int n = i >> 7, kk = i & 127;
            dstH[n * (BROW / 2) + kk] = srcH[i];
            dstL[n * (BROW / 2) + kk] = srcL[i];
        }
    }
    __syncthreads();

    // per-lane bias (4 n8-tiles per warp)
    float2 bb[4];
    #pragma unroll
    for (int j = 0; j < 4; j++)
        bb[j] = *(const float2*)(g_biasp + wrow + n0 + wn * 32 + j * 8 + qc);

    const uint32_t sbase = smem_u32(bsm);
    const int lm = lane >> 3, lr = lane & 7;
    const uint32_t rowb =
        (uint32_t)((((lm >> 1) * 8 + lr) * BROW + (lm & 1) * 8) * 2);

    const int ntiles = M >> 7;
    for (int tile = blockIdx.y; tile < ntiles; tile += gridDim.y) {
        const size_t m0 = (size_t)tile << 7;

        float c[2][4][4];
        #pragma unroll
        for (int i = 0; i < 2; i++)
            #pragma unroll
            for (int j = 0; j < 4; j++)
                c[i][j][0] = c[i][j][1] = c[i][j][2] = c[i][j][3] = 0.f;

        const float* a0 = A + (m0 + wm * 32 + g) * 256 + qc;
        const float* a1 = a0 + 16 * 256;

        float2 vbuf[2][2][4];
        {
            vbuf[0][0][0] = *(const float2*)(a0);
            vbuf[0][0][1] = *(const float2*)(a0 + 2048);
            vbuf[0][0][2] = *(const float2*)(a0 + 8);
            vbuf[0][0][3] = *(const float2*)(a0 + 2056);
            vbuf[0][1][0] = *(const float2*)(a1);
            vbuf[0][1][1] = *(const float2*)(a1 + 2048);
            vbuf[0][1][2] = *(const float2*)(a1 + 8);
            vbuf[0][1][3] = *(const float2*)(a1 + 2056);
        }

        #pragma unroll 4
        for (int ks = 0; ks < 16; ks++) {
            const int k0 = ks * 16;
            float2 (&v)[2][4] = vbuf[ks & 1];

            if (ks < 15) {
                float2 (&vn)[2][4] = vbuf[(ks + 1) & 1];
                const float* p0 = a0 + k0 + 16;
                const float* p1 = a1 + k0 + 16;
                vn[0][0] = *(const float2*)(p0);
                vn[0][1] = *(const float2*)(p0 + 2048);
                vn[0][2] = *(const float2*)(p0 + 8);
                vn[0][3] = *(const float2*)(p0 + 2056);
                vn[1][0] = *(const float2*)(p1);
                vn[1][1] = *(const float2*)(p1 + 2048);
                vn[1][2] = *(const float2*)(p1 + 8);
                vn[1][3] = *(const float2*)(p1 + 2056);
            }

            uint32_t ah[2][4], al[2][4];
            #pragma unroll
            for (int i = 0; i < 2; i++) {
                cvt_hilo(v[i][0].x, v[i][0].y, ah[i][0], al[i][0]);
                cvt_hilo(v[i][1].x, v[i][1].y, ah[i][1], al[i][1]);
                cvt_hilo(v[i][2].x, v[i][2].y, ah[i][2], al[i][2]);
                cvt_hilo(v[i][3].x, v[i][3].y, ah[i][3], al[i][3]);
            }

            // B fragments: 4 n8-tiles (32 cols), hi and lo
            uint32_t bh[4][2], bl[4][2];
            #pragma unroll
            for (int jj = 0; jj < 2; jj++) {
                uint32_t off =
                    (uint32_t)(((wn * 32 + jj * 16) * BROW + k0) * 2) + rowb;
                uint32_t r4[4];
                ldm_x4(r4, sbase + off);
                bh[2 * jj][0] = r4[0]; bh[2 * jj][1] = r4[1];
                bh[2 * jj + 1][0] = r4[2]; bh[2 * jj + 1][1] = r4[3];
                ldm_x4(r4, sbase + 2 * BPLANE + off);
                bl[2 * jj][0] = r4[0]; bl[2 * jj][1] = r4[1];
                bl[2 * jj + 1][0] = r4[2]; bl[2 * jj + 1][1] = r4[3];
            }

            #pragma unroll
            for (int i = 0; i < 2; i++)
                #pragma unroll
                for (int j = 0; j < 4; j++) {
                    mma16816(c[i][j], ah[i], bh[j]);
                    mma16816(c[i][j], ah[i], bl[j]);
                    mma16816(c[i][j], al[i], bh[j]);
                }
        }

        // ---- epilogue: bias (+ residual) -> C ----
        #pragma unroll
        for (int i = 0; i < 2; i++) {
            size_t row = m0 + wm * 32 + i * 16 + g;
            #pragma unroll
            for (int j = 0; j < 4; j++) {
                int col = n0 + wn * 32 + j * 8 + qc;
                float2 o0, o1;
                o0.x = c[i][j][0] + bb[j].x;
                o0.y = c[i][j][1] + bb[j].y;
                o1.x = c[i][j][2] + bb[j].x;
                o1.y = c[i][j][3] + bb[j].y;
                if (res) {
                    float2 r0 = *(const float2*)(res + row * (size_t)ldc + col);
                    float2 r1 = *(const float2*)(res + (row + 8) * (size_t)ldc + col);
                    o0.x += r0.x; o0.y += r0.y;
                    o1.x += r1.x; o1.y += r1.y;
                }
                *(float2*)(C + row * (size_t)ldc + col) = o0;
                *(float2*)(C + (row + 8) * (size_t)ldc + col) = o1;
            }
        }
    }
}

// ---------------------------------------------------------------------------
// Sampler, two-phase:
//  setup : precompute, per (q,h,p): 4 final BYTE offsets into the value slice
//          + softmax-folded validity-zeroed corner weights.
//  gather: warp = head, lane = channel; LDS.128 x2 + 4x(add+LDG+FFMA).
// ---------------------------------------------------------------------------
__global__ __launch_bounds__(256) void sample_k(const float* __restrict__ ref2d)
{
    __shared__ float  lg[16][128];
    __shared__ float  refs[32];
    __shared__ int4   smO[512];       // [q][h][p] byte offsets of 4 corners
    __shared__ float4 smW[512];       // [q][h][p] folded corner weights

    int tid = threadIdx.x;
    int b  = blockIdx.x >> 9;            // 512 blocks per batch
    int q0 = (blockIdx.x & 511) << 4;

    const float4* lsrc = (const float4*)(g_logit + ((size_t)b * NQL + q0) * 128);
    #pragma unroll
    for (int i = 0; i < 2; i++) {
        int f = tid + i * 256;
        ((float4*)&lg[0][0])[f] = lsrc[f];
    }
    if (tid < 32) refs[tid] = ref2d[((size_t)b * NQL + q0) * 2 + tid];
    __syncthreads();

    // ---- setup: 2 threads per (q,h), 2 points each ----
    {
        int cb = tid >> 1;               // 0..127 = q*8+h
        int q  = cb >> 3, h = cb & 7;
        int pbase = (tid & 1) * 2;

        float l0 = lg[q][64 + h * 4 + 0];
        float l1 = lg[q][64 + h * 4 + 1];
        float l2 = lg[q][64 + h * 4 + 2];
        float l3 = lg[q][64 + h * 4 + 3];
        float m = fmaxf(fmaxf(l0, l1), fmaxf(l2, l3));
        float e0 = __expf(l0 - m), e1 = __expf(l1 - m);
        float e2 = __expf(l2 - m), e3 = __expf(l3 - m);
        float inv = 1.f / (e0 + e1 + e2 + e3);
        float aw[4] = {e0 * inv, e1 * inv, e2 * inv, e3 * inv};

        float refx = refs[2 * q], refy = refs[2 * q + 1];

        #pragma unroll
        for (int pp = 0; pp < 2; pp++) {
            int p = pbase + pp;
            float offx = lg[q][h * 8 + 2 * p + 0];
            float offy = lg[q][h * 8 + 2 * p + 1];
            float x = fmaf(refx, (float)WGRID, offx) - 0.5f;
            float y = fmaf(refy, (float)HGRID, offy) - 0.5f;
            float x0f = floorf(x), y0f = floorf(y);
            int ix0 = (int)x0f, iy0 = (int)y0f;
            int ix1 = ix0 + 1, iy1 = iy0 + 1;
            float wx1 = x - x0f, wx0 = 1.f - wx1;
            float wy1 = y - y0f, wy0 = 1.f - wy1;

            bool vx0 = (unsigned)ix0 < WGRID;
            bool vx1 = (unsigned)ix1 < WGRID;
            bool vy0 = (unsigned)iy0 < HGRID;
            bool vy1 = (unsigned)iy1 < HGRID;

            float ap = aw[p];
            float4 w;
            w.x = (vx0 & vy0) ? ap * wx0 * wy0 : 0.f;
            w.y = (vx1 & vy0) ? ap * wx1 * wy0 : 0.f;
            w.z = (vx0 & vy1) ? ap * wx0 * wy1 : 0.f;
            w.w = (vx1 & vy1) ? ap * wx1 * wy1 : 0.f;

            int x0c = min(max(ix0, 0), WGRID - 1);
            int x1c = min(max(ix1, 0), WGRID - 1);
            int y0c = min(max(iy0, 0), HGRID - 1);
            int y1c = min(max(iy1, 0), HGRID - 1);

            // byte offsets: ((y*128 + x) * 256 floats) * 4B = ((y<<7)+x)<<10
            int r0 = y0c << 7, r1 = y1c << 7;
            int idx = cb * 4 + p;
            smO[idx] = make_int4((r0 + x0c) << 10, (r0 + x1c) << 10,
                                 (r1 + x0c) << 10, (r1 + x1c) << 10);
            smW[idx] = w;
        }
    }
    __syncthreads();

    // ---- gather ----
    int h = tid >> 5, lane = tid & 31;
    const char* vbc = (const char*)(g_v + (size_t)b * NVL * EDIM + h * DH + lane);
    float* mb = g_mid + ((size_t)b * NQL + q0) * EDIM + h * DH + lane;

    #pragma unroll 4
    for (int q = 0; q < 16; q++) {
        int base = (q * 8 + h) * 4;
        float out = 0.f;
        #pragma unroll
        for (int p = 0; p < NP; p++) {
            int4   o = smO[base + p];
            float4 w = smW[base + p];
            out = fmaf(w.x, *(const float*)(vbc + o.x), out);
            out = fmaf(w.y, *(const float*)(vbc + o.y), out);
            out = fmaf(w.z, *(const float*)(vbc + o.z), out);
            out = fmaf(w.w, *(const float*)(vbc + o.w), out);
        }
        mb[(size_t)q * EDIM] = out;
    }
}

// ---------------------------------------------------------------------------
extern "C" void kernel_launch(void* const* d_in, const int* in_sizes, int n_in,
                              void* d_out, int out_size)
{
    const float* query = (const float*)d_in[0];
    const float* value = (const float*)d_in[1];
    const float* ref2d = (const float*)d_in[2];
    // d_in[3] spatial_shapes: fixed 128x128, hardcoded
    const float* Woff  = (const float*)d_in[4];
    const float* boff  = (const float*)d_in[5];
    const float* Wattn = (const float*)d_in[6];
    const float* battn = (const float*)d_in[7];
    const float* Wval  = (const float*)d_in[8];
    const float* bval  = (const float*)d_in[9];
    const float* Wout  = (const float*)d_in[10];
    const float* bout  = (const float*)d_in[11];
    float* out = (float*)d_out;

    float *vptr, *midptr, *lptr;
    cudaGetSymbolAddress((void**)&vptr,   g_v);
    cudaGetSymbolAddress((void**)&midptr, g_mid);
    cudaGetSymbolAddress((void**)&lptr,   g_logit);

    cudaFuncSetAttribute(hmma_gemm_k,
                         cudaFuncAttributeMaxDynamicSharedMemorySize, GSMEM);

    // 0) pack all weights -> bf16 hi/lo planes (+ padded biases)
    pack_w_k<<<640, 256>>>(Wval, Woff, Wattn, Wout, bval, boff, battn, bout);

    // 1) value projection: g_v = value @ W_val + b_val     (131072 x 256 x 256)
    hmma_gemm_k<<<dim3(2, 74), NTHR, GSMEM>>>(
        value, nullptr, vptr, 0, NB * NVL, 256);

    // 2) logits: g_logit = query @ [W_off|W_attn|0] + bias (65536 x 128 x 256)
    hmma_gemm_k<<<dim3(1, 148), NTHR, GSMEM>>>(
        query, nullptr, lptr, 256, NB * NQL, 128);

    // 3) softmax + bilinear sampling -> g_mid
    sample_k<<<NB * NQL / 16, 256>>>(ref2d);

    // 4) output projection + bias + residual -> out
    hmma_gemm_k<<<dim3(2, 74), NTHR, GSMEM>>>(
        midptr, query, out, 384, NB * NQL, 256);
}